// round 1
// baseline (speedup 1.0000x reference)
#include <cuda_runtime.h>

// Shapes (compile-time; reference fixes B=4096, N=64, D=32, H=64)
#define NJ 64
#define DD 32
#define HH 64

// Shared memory layout (float offsets)
#define S_WM1 0                    // [64][64]  = 4096
#define S_WM2 (S_WM1 + 4096)       // [64][32]  = 2048
#define S_WU1 (S_WM2 + 2048)       // [64][64]  = 4096
#define S_WU2 (S_WU1 + 4096)       // [64][32]  = 2048
#define S_B   (S_WU2 + 2048)       // bm1[64] bm2[32] bu1[64] bu2[32] = 192
#define S_F   (S_B + 192)          // [64][33]  = 2112  (padded)
#define S_G   (S_F + 2112)         // [64][129] = 8256  (G1|G2, padded; reused as U[64][65])
#define S_M   (S_G + 8256)         // [64][33]  = 2112  (scatter target)
#define S_TOTAL (S_M + 2112)       // 24960 floats = 99840 bytes

extern __shared__ float sm[];

__global__ void __launch_bounds__(256, 2)
agn_kernel(const float* __restrict__ Fg,
           const float* __restrict__ Wm1, const float* __restrict__ bm1,
           const float* __restrict__ Wm2, const float* __restrict__ bm2,
           const float* __restrict__ Wu1, const float* __restrict__ bu1,
           const float* __restrict__ Wu2, const float* __restrict__ bu2,
           const float* __restrict__ rwp,
           float* __restrict__ Og)
{
    const int b = blockIdx.x;
    const int t = threadIdx.x;

    // ---- load weights / biases / features into smem (coalesced) ----
    #pragma unroll
    for (int i = 0; i < 16; i++) sm[S_WM1 + t + i*256] = Wm1[t + i*256];
    #pragma unroll
    for (int i = 0; i < 8; i++)  sm[S_WM2 + t + i*256] = Wm2[t + i*256];
    #pragma unroll
    for (int i = 0; i < 16; i++) sm[S_WU1 + t + i*256] = Wu1[t + i*256];
    #pragma unroll
    for (int i = 0; i < 8; i++)  sm[S_WU2 + t + i*256] = Wu2[t + i*256];
    if (t < 64)        sm[S_B + t]       = bm1[t];
    else if (t < 96)   sm[S_B + t]       = bm2[t - 64];
    else if (t < 160)  sm[S_B + t]       = bu1[t - 96];
    else if (t < 192)  sm[S_B + t]       = bu2[t - 160];

    const float* Fb = Fg + (size_t)b * (NJ * DD);
    #pragma unroll
    for (int i = 0; i < 8; i++) {
        int idx = t + i * 256;
        int n = idx >> 5, d = idx & 31;
        sm[S_F + n*33 + d] = Fb[idx];
    }
    __syncthreads();

    // ---- Stage 1: G1 = F @ Wm1[0:32,:], G2 = F @ Wm1[32:64,:] ----
    // thread -> (node n, half g, h-quarter q of 32)
    {
        const int n = t & 63;
        const int g = (t >> 6) & 1;
        const int q = t >> 7;
        float f[32];
        #pragma unroll
        for (int d = 0; d < 32; d++) f[d] = sm[S_F + n*33 + d];
        float acc[32];
        #pragma unroll
        for (int h = 0; h < 32; h++) acc[h] = 0.f;
        const float* W = sm + S_WM1 + g*2048 + q*32;   // row d of chosen half, col block q*32
        #pragma unroll
        for (int d = 0; d < 32; d++) {
            const float4* wr = reinterpret_cast<const float4*>(W + d*64);
            const float fd = f[d];
            #pragma unroll
            for (int h4 = 0; h4 < 8; h4++) {
                float4 w = wr[h4];
                acc[h4*4+0] = fmaf(fd, w.x, acc[h4*4+0]);
                acc[h4*4+1] = fmaf(fd, w.y, acc[h4*4+1]);
                acc[h4*4+2] = fmaf(fd, w.z, acc[h4*4+2]);
                acc[h4*4+3] = fmaf(fd, w.w, acc[h4*4+3]);
            }
        }
        float* dst = sm + S_G + n*129 + g*64 + q*32;
        #pragma unroll
        for (int h = 0; h < 32; h++) dst[h] = acc[h];
    }
    __syncthreads();

    // ---- Stage 2: per-edge message MLP + scatter ----
    // 2 threads per edge (126 edges); each handles 16 of 32 output dims.
    // Edge e<63: dst=e, src=e+1 (msgA). Edge e>=63: j=e-63, dst=j+1, src=j (msgB).
    {
        float acc[16];
        const int e  = t >> 1;
        const int d0 = (t & 1) * 16;
        if (t < 252) {
            int dn, sn;
            if (e < 63) { dn = e;      sn = e + 1; }
            else        { dn = e - 62; sn = e - 63; }
            const float* g1 = sm + S_G + dn*129;
            const float* g2 = sm + S_G + sn*129 + 64;
            float h1[64];
            #pragma unroll
            for (int h = 0; h < 64; h++) {
                float v = g1[h] + g2[h] + sm[S_B + h];
                h1[h] = fmaxf(v, 0.f);
            }
            #pragma unroll
            for (int j = 0; j < 16; j++) acc[j] = sm[S_B + 64 + d0 + j];
            #pragma unroll
            for (int h = 0; h < 64; h++) {
                const float4* wr = reinterpret_cast<const float4*>(sm + S_WM2 + h*32 + d0);
                const float hv = h1[h];
                #pragma unroll
                for (int j4 = 0; j4 < 4; j4++) {
                    float4 w = wr[j4];
                    acc[j4*4+0] = fmaf(hv, w.x, acc[j4*4+0]);
                    acc[j4*4+1] = fmaf(hv, w.y, acc[j4*4+1]);
                    acc[j4*4+2] = fmaf(hv, w.z, acc[j4*4+2]);
                    acc[j4*4+3] = fmaf(hv, w.w, acc[j4*4+3]);
                }
            }
            #pragma unroll
            for (int j = 0; j < 16; j++) acc[j] = fmaxf(acc[j], 0.f);
        }
        // phase A: msgA (dst = e for e<63) stores; spare threads zero node-63 row
        if (t < 126) {
            float* m = sm + S_M + e*33 + d0;
            #pragma unroll
            for (int j = 0; j < 16; j++) m[j] = acc[j];
        } else if (t >= 252) {
            int j0 = (t - 252) * 8;
            #pragma unroll
            for (int j = 0; j < 8; j++) sm[S_M + 63*33 + j0 + j] = 0.f;
        }
        __syncthreads();
        // phase B: msgB (dst = e-62) accumulates
        if (t >= 126 && t < 252) {
            const int dn = e - 62;
            float* m = sm + S_M + dn*33 + d0;
            #pragma unroll
            for (int j = 0; j < 16; j++) m[j] += acc[j];
        }
        __syncthreads();
    }

    // ---- Stage 3: U = relu([F | M] @ Wu1 + bu1), stored into S_G (stride 65) ----
    {
        const int n = t & 63;
        const int q = t >> 6;          // 4 h-blocks of 16
        float acc[16];
        #pragma unroll
        for (int j = 0; j < 16; j++) acc[j] = sm[S_B + 96 + q*16 + j];
        #pragma unroll
        for (int d = 0; d < 32; d++) {
            const float fv = sm[S_F + n*33 + d];
            const float4* wr = reinterpret_cast<const float4*>(sm + S_WU1 + d*64 + q*16);
            #pragma unroll
            for (int j4 = 0; j4 < 4; j4++) {
                float4 w = wr[j4];
                acc[j4*4+0] = fmaf(fv, w.x, acc[j4*4+0]);
                acc[j4*4+1] = fmaf(fv, w.y, acc[j4*4+1]);
                acc[j4*4+2] = fmaf(fv, w.z, acc[j4*4+2]);
                acc[j4*4+3] = fmaf(fv, w.w, acc[j4*4+3]);
            }
        }
        #pragma unroll
        for (int d = 0; d < 32; d++) {
            const float mv = sm[S_M + n*33 + d];
            const float4* wr = reinterpret_cast<const float4*>(sm + S_WU1 + (32+d)*64 + q*16);
            #pragma unroll
            for (int j4 = 0; j4 < 4; j4++) {
                float4 w = wr[j4];
                acc[j4*4+0] = fmaf(mv, w.x, acc[j4*4+0]);
                acc[j4*4+1] = fmaf(mv, w.y, acc[j4*4+1]);
                acc[j4*4+2] = fmaf(mv, w.z, acc[j4*4+2]);
                acc[j4*4+3] = fmaf(mv, w.w, acc[j4*4+3]);
            }
        }
        float* u = sm + S_G + n*65 + q*16;   // S_G reused (stage-2 data dead)
        #pragma unroll
        for (int j = 0; j < 16; j++) u[j] = fmaxf(acc[j], 0.f);
    }
    __syncthreads();

    // ---- Stage 4: out = rw*(U @ Wu2 + bu2) + (1-rw)*F, coalesced store ----
    {
        const int n = t >> 2;
        const int q = t & 3;           // 4 d-blocks of 8
        float acc[8];
        #pragma unroll
        for (int j = 0; j < 8; j++) acc[j] = sm[S_B + 160 + q*8 + j];
        #pragma unroll
        for (int h = 0; h < 64; h++) {
            const float uv = sm[S_G + n*65 + h];
            const float4* wr = reinterpret_cast<const float4*>(sm + S_WU2 + h*32 + q*8);
            #pragma unroll
            for (int j4 = 0; j4 < 2; j4++) {
                float4 w = wr[j4];
                acc[j4*4+0] = fmaf(uv, w.x, acc[j4*4+0]);
                acc[j4*4+1] = fmaf(uv, w.y, acc[j4*4+1]);
                acc[j4*4+2] = fmaf(uv, w.z, acc[j4*4+2]);
                acc[j4*4+3] = fmaf(uv, w.w, acc[j4*4+3]);
            }
        }
        const float rw = *rwp;
        const float cw = 1.f - rw;
        float4 o[2];
        float* of = reinterpret_cast<float*>(o);
        #pragma unroll
        for (int j = 0; j < 8; j++) {
            float fv = sm[S_F + n*33 + q*8 + j];
            of[j] = rw * acc[j] + cw * fv;
        }
        float4* og = reinterpret_cast<float4*>(Og + (size_t)b*2048 + n*32 + q*8);
        og[0] = o[0];
        og[1] = o[1];
    }
}

extern "C" void kernel_launch(void* const* d_in, const int* in_sizes, int n_in,
                              void* d_out, int out_size) {
    const float* Fg  = (const float*)d_in[0];
    const float* Wm1 = (const float*)d_in[1];
    const float* bm1 = (const float*)d_in[2];
    const float* Wm2 = (const float*)d_in[3];
    const float* bm2 = (const float*)d_in[4];
    const float* Wu1 = (const float*)d_in[5];
    const float* bu1 = (const float*)d_in[6];
    const float* Wu2 = (const float*)d_in[7];
    const float* bu2 = (const float*)d_in[8];
    const float* rwp = (const float*)d_in[9];
    float* Og = (float*)d_out;

    const int B = in_sizes[0] / (NJ * DD);   // 4096
    const int smem_bytes = S_TOTAL * sizeof(float);   // ~97.5 KB

    static bool attr_set = false;
    if (!attr_set) {
        cudaFuncSetAttribute(agn_kernel,
                             cudaFuncAttributeMaxDynamicSharedMemorySize, smem_bytes);
        attr_set = true;
    }

    agn_kernel<<<B, 256, smem_bytes>>>(Fg, Wm1, bm1, Wm2, bm2,
                                       Wu1, bu1, Wu2, bu2, rwp, Og);
}